// round 7
// baseline (speedup 1.0000x reference)
#include <cuda_runtime.h>
#include <math.h>

#define B 64
#define N 8192
#define M 128
#define EPS 1e-16f
#define EPS_COS 1e-8f

// ---------------- scratch (no allocation allowed) ----------------
__device__ float g_cos[B * N];            // 2 MB
__device__ float g_w[B * N];              // 2 MB
__device__ float g_pr[B * 128 * M];       // 4 MB partial r: [B][128 blocks][M]
__device__ unsigned int g_cnt_c[B];       // ticket counters: cos->addr fusion
__device__ unsigned int g_cnt_w[B];       // ticket counters: write->r fusion

// padded shared index: bank = (i + i/32) & 31 -> conflict-free for both
// strided (i = tid + j*256) and chunked (i = tid*32 + off) access patterns
#define P(i) ((i) + ((i) >> 5))

// ============ kernel 1: cosine similarity + fused addressing ============
// grid (N/64, B), 256 threads. Last-finishing block per batch runs the
// softmax/interpolate/shift/sharpen phase for that batch (ticket pattern).
#define CROWS 64
__global__ __launch_bounds__(256) void cos_addr_kernel(
    const float* __restrict__ mem, const float* __restrict__ k,
    const float* __restrict__ beta, const float* __restrict__ g,
    const float* __restrict__ s, const float* __restrict__ gamma,
    const float* __restrict__ w_prev)
{
    __shared__ float4 ks[32];          // k + EPS
    __shared__ float s_invnk;
    __shared__ float sw[N + N / 32];   // padded, 33 KB (addr phase)
    __shared__ float red[8];
    __shared__ bool is_last;

    int b = blockIdx.y;
    int tid = threadIdx.x;

    // ---- cos phase ----
    if (tid < 32) {
        float4 k4 = reinterpret_cast<const float4*>(k + b * M)[tid];
        k4.x += EPS; k4.y += EPS; k4.z += EPS; k4.w += EPS;
        ks[tid] = k4;
        float nk2 = k4.x * k4.x + k4.y * k4.y + k4.z * k4.z + k4.w * k4.w;
        #pragma unroll
        for (int t = 16; t > 0; t >>= 1) nk2 += __shfl_xor_sync(0xffffffffu, nk2, t);
        if (tid == 0) s_invnk = 1.f / fmaxf(sqrtf(nk2), EPS_COS);
    }
    __syncthreads();

    int warp = tid >> 5, lane = tid & 31;
    int sub = lane >> 3, lane8 = lane & 7;   // 4 row-groups of 8 lanes
    int n0 = blockIdx.x * CROWS;
    float invnk = s_invnk;

    #pragma unroll
    for (int iter = 0; iter < 2; ++iter) {
        int row = n0 + iter * 32 + warp * 4 + sub;
        const float4* mp = reinterpret_cast<const float4*>(
            mem + ((size_t)b * N + row) * M);

        float dot = 0.f, nm2 = 0.f;
        #pragma unroll
        for (int j = 0; j < 4; ++j) {
            float4 m4 = __ldcs(mp + lane8 + j * 8);   // streaming: no reuse
            float4 k4 = ks[lane8 + j * 8];
            float mx = m4.x + EPS, my = m4.y + EPS, mz = m4.z + EPS, mw = m4.w + EPS;
            dot += mx * k4.x + my * k4.y + mz * k4.z + mw * k4.w;
            nm2 += mx * mx + my * my + mz * mz + mw * mw;
        }
        #pragma unroll
        for (int t = 4; t > 0; t >>= 1) {
            dot += __shfl_xor_sync(0xffffffffu, dot, t);
            nm2 += __shfl_xor_sync(0xffffffffu, nm2, t);
        }
        if (lane8 == 0) {
            float nm = fmaxf(sqrtf(nm2), EPS_COS);
            g_cos[(size_t)b * N + row] = dot * invnk / nm;
        }
    }

    // ---- ticket: last block of this batch runs the addr phase ----
    __threadfence();
    if (tid == 0) {
        unsigned int v = atomicAdd(&g_cnt_c[b], 1u);
        is_last = (v == (N / CROWS) - 1u);
        if (is_last) g_cnt_c[b] = 0;   // self-reset for next graph replay
    }
    __syncthreads();
    if (!is_last) return;

    // ---- addr phase (256 threads, 32 elems/thread) ----
    float betav = beta[b], gv = g[b], gammav = gamma[b];
    float s0 = s[b * 3 + 0], s1 = s[b * 3 + 1], s2 = s[b * 3 + 2];
    const float* cp = g_cos + (size_t)b * N;

    // pass A: v = beta*cos -> shared, block max
    float mx = -1e30f;
    #pragma unroll
    for (int j = 0; j < N / 256; ++j) {
        int i = tid + j * 256;
        float v = betav * cp[i];
        sw[P(i)] = v;
        mx = fmaxf(mx, v);
    }
    #pragma unroll
    for (int t = 16; t > 0; t >>= 1) mx = fmaxf(mx, __shfl_xor_sync(0xffffffffu, mx, t));
    if (lane == 0) red[warp] = mx;
    __syncthreads();
    float bmx = red[0];
    #pragma unroll
    for (int w = 1; w < 8; ++w) bmx = fmaxf(bmx, red[w]);

    // pass B: exp + sum
    float sum = 0.f;
    #pragma unroll
    for (int j = 0; j < N / 256; ++j) {
        int i = tid + j * 256;
        float ev = __expf(sw[P(i)] - bmx);
        sw[P(i)] = ev;
        sum += ev;
    }
    #pragma unroll
    for (int t = 16; t > 0; t >>= 1) sum += __shfl_xor_sync(0xffffffffu, sum, t);
    __syncthreads();
    if (lane == 0) red[warp] = sum;
    __syncthreads();
    float bsum = 0.f;
    #pragma unroll
    for (int w = 0; w < 8; ++w) bsum += red[w];
    float inv = 1.f / bsum;

    // wg = g*wc + (1-g)*w_prev
    #pragma unroll
    for (int j = 0; j < N / 256; ++j) {
        int i = tid + j * 256;
        sw[P(i)] = gv * (sw[P(i)] * inv) + (1.f - gv) * w_prev[(size_t)b * N + i];
    }
    __syncthreads();

    // circular shift + sharpen, in place via rolling registers over a
    // contiguous 32-elem chunk per thread. Boundary values captured first.
    int c0 = tid * 32;
    float left  = sw[P((c0 == 0) ? (N - 1) : (c0 - 1))];
    float right = sw[P((c0 + 32 == N) ? 0 : (c0 + 32))];
    __syncthreads();   // all boundary reads done before any overwrite

    float prev = left, sum2 = 0.f;
    #pragma unroll
    for (int off = 0; off < 32; ++off) {
        int i = c0 + off;
        float cur = sw[P(i)];
        float nxt = (off == 31) ? right : sw[P(i + 1)];
        float wh = s0 * prev + s1 * cur + s2 * nxt;
        float ww = __expf(gammav * __logf(wh));  // wh > 0 always
        sw[P(i)] = ww;
        sum2 += ww;
        prev = cur;
    }
    #pragma unroll
    for (int t = 16; t > 0; t >>= 1) sum2 += __shfl_xor_sync(0xffffffffu, sum2, t);
    if (lane == 0) red[warp] = sum2;
    __syncthreads();
    float bsum2 = 0.f;
    #pragma unroll
    for (int w = 0; w < 8; ++w) bsum2 += red[w];
    float inv2 = 1.f / (bsum2 + EPS);

    #pragma unroll
    for (int j = 0; j < N / 256; ++j) {
        int i = tid + j * 256;
        g_w[(size_t)b * N + i] = sw[P(i)] * inv2;
    }
}

// ============ kernel 2: new_mem write + fused r reduction ============
// grid (128, B), 256 threads; each block: 64 rows of one batch.
#define ROWS_PER_BLK 64
__global__ __launch_bounds__(256) void write_kernel(
    const float* __restrict__ mem, const float* __restrict__ e,
    const float* __restrict__ a, float* __restrict__ newmem,
    float* __restrict__ r_out)
{
    int b = blockIdx.y;
    int blk = blockIdx.x;              // 0..127
    int t = threadIdx.x;
    int m4 = t & 31;                   // float4 index along M
    int grp = t >> 5;                  // 8 row groups

    const float4 e4 = reinterpret_cast<const float4*>(e + b * M)[m4];
    const float4 a4 = reinterpret_cast<const float4*>(a + b * M)[m4];

    int n0 = blk * ROWS_PER_BLK;
    size_t base = ((size_t)b * N + n0) * M;
    const float4* mp = reinterpret_cast<const float4*>(mem + base);
    float4* op = reinterpret_cast<float4*>(newmem + base);
    const float* wp = g_w + (size_t)b * N + n0;

    float4 racc = make_float4(0.f, 0.f, 0.f, 0.f);
    #pragma unroll
    for (int it = 0; it < ROWS_PER_BLK / 8; ++it) {
        int row = it * 8 + grp;
        float wv = __ldg(wp + row);
        float4 mv = __ldcs(mp + row * 32 + m4);   // streaming read
        float4 o;
        o.x = mv.x * (1.f - wv * e4.x) + wv * a4.x;
        o.y = mv.y * (1.f - wv * e4.y) + wv * a4.y;
        o.z = mv.z * (1.f - wv * e4.z) + wv * a4.z;
        o.w = mv.w * (1.f - wv * e4.w) + wv * a4.w;
        __stcs(op + row * 32 + m4, o);            // streaming write
        racc.x += wv * mv.x;
        racc.y += wv * mv.y;
        racc.z += wv * mv.z;
        racc.w += wv * mv.w;
    }

    __shared__ float4 sd[256];
    __shared__ bool is_last;
    sd[t] = racc;
    __syncthreads();
    #pragma unroll
    for (int s = 4; s > 0; s >>= 1) {
        if (grp < s) {
            float4 o = sd[t + s * 32];
            sd[t].x += o.x; sd[t].y += o.y; sd[t].z += o.z; sd[t].w += o.w;
        }
        __syncthreads();
    }
    if (grp == 0) {
        reinterpret_cast<float4*>(g_pr + ((size_t)b * 128 + blk) * M)[m4] = sd[t];
    }

    // ticket: last block of this batch reduces the 128 partials (L2-hot)
    __threadfence();
    if (t == 0) {
        unsigned int v = atomicAdd(&g_cnt_w[b], 1u);
        is_last = (v == 127u);
        if (is_last) g_cnt_w[b] = 0;   // self-reset for next graph replay
    }
    __syncthreads();
    if (!is_last) return;

    float4 acc = make_float4(0.f, 0.f, 0.f, 0.f);
    const float4* pp = reinterpret_cast<const float4*>(g_pr + (size_t)b * 128 * M);
    #pragma unroll
    for (int j = 0; j < 16; ++j) {
        float4 v = pp[(grp + j * 8) * 32 + m4];
        acc.x += v.x; acc.y += v.y; acc.z += v.z; acc.w += v.w;
    }
    __syncthreads();
    sd[t] = acc;
    __syncthreads();
    #pragma unroll
    for (int s = 4; s > 0; s >>= 1) {
        if (grp < s) {
            float4 o = sd[t + s * 32];
            sd[t].x += o.x; sd[t].y += o.y; sd[t].z += o.z; sd[t].w += o.w;
        }
        __syncthreads();
    }
    if (grp == 0) {
        reinterpret_cast<float4*>(r_out + b * M)[m4] = sd[t];
    }
}

// ---------------- launch ----------------
extern "C" void kernel_launch(void* const* d_in, const int* in_sizes, int n_in,
                              void* d_out, int out_size) {
    const float* memory = (const float*)d_in[0];
    const float* k      = (const float*)d_in[1];
    const float* beta   = (const float*)d_in[2];
    const float* g      = (const float*)d_in[3];
    const float* s      = (const float*)d_in[4];
    const float* gamma  = (const float*)d_in[5];
    const float* w_prev = (const float*)d_in[6];
    const float* e      = (const float*)d_in[7];
    const float* a      = (const float*)d_in[8];

    float* r_out  = (float*)d_out;            // [B, M]
    float* nm_out = (float*)d_out + B * M;    // [B, N, M]

    // kernel 1: cos + fused addressing (ticketed per batch)
    dim3 grid1(N / CROWS, B);
    cos_addr_kernel<<<grid1, 256>>>(memory, k, beta, g, s, gamma, w_prev);

    // kernel 2: write + fused deterministic r reduction
    dim3 grid3(N / ROWS_PER_BLK, B);
    write_kernel<<<grid3, 256>>>(memory, e, a, nm_out, r_out);
}